// round 1
// baseline (speedup 1.0000x reference)
#include <cuda_runtime.h>

// Problem constants
#define BB  2
#define SS  2048
#define DD  1024
#define HH  16
#define HDD 64
#define BHH (BB*HH)   // 32

// Scratch (allocation-free rule: __device__ globals)
__device__ float g_q [BHH*SS*HDD];   // [bh][s][hd]
__device__ float g_k [BHH*SS*HDD];
__device__ float g_v [BHH*SS*HDD];
__device__ float g_ao[BB*SS*DD];     // [b][s][h*64+hd]

// ---------------------------------------------------------------------------
// 128x128x16 fp32 SGEMM, 256 threads, 8x8 per thread.
// MODE 0: C = A@B + bias, scattered into g_q/g_k/g_v (QKV projection)
// MODE 1: C = g_ao@B + bias, written to Cout (output projection)
// ---------------------------------------------------------------------------
template<int MODE>
__global__ __launch_bounds__(256)
void sgemm128(const float* __restrict__ A,
              const float* __restrict__ Bg,
              const float* __restrict__ bias,
              float* __restrict__ Cout,
              int M, int N, int K)
{
    __shared__ float As[16][128];   // A tile transposed: As[k][m]
    __shared__ float Bs[16][128];   // B tile natural:    Bs[k][n]

    const float* Ap = (MODE == 0) ? A : g_ao;

    const int bm  = blockIdx.y * 128;
    const int bn  = blockIdx.x * 128;
    const int tid = threadIdx.x;
    const int tx  = tid & 15;
    const int ty  = tid >> 4;

    float acc[8][8];
    #pragma unroll
    for (int i = 0; i < 8; i++)
        #pragma unroll
        for (int j = 0; j < 8; j++) acc[i][j] = 0.f;

    for (int k0 = 0; k0 < K; k0 += 16) {
        __syncthreads();
        #pragma unroll
        for (int r = 0; r < 2; r++) {
            int f = tid + r * 256;
            // A tile: 128 rows x 16 k  (512 float4)
            int arow = f >> 2;
            int akq  = (f & 3) << 2;
            float4 av = *(const float4*)(Ap + (bm + arow) * K + k0 + akq);
            As[akq + 0][arow] = av.x;
            As[akq + 1][arow] = av.y;
            As[akq + 2][arow] = av.z;
            As[akq + 3][arow] = av.w;
            // B tile: 16 k x 128 n (512 float4)
            int brow = f >> 5;
            int bcol = (f & 31) << 2;
            *(float4*)&Bs[brow][bcol] =
                *(const float4*)(Bg + (k0 + brow) * N + bn + bcol);
        }
        __syncthreads();
        #pragma unroll
        for (int kk = 0; kk < 16; kk++) {
            float av[8], bv[8];
            *(float4*)&av[0] = *(float4*)&As[kk][ty * 8];
            *(float4*)&av[4] = *(float4*)&As[kk][ty * 8 + 4];
            *(float4*)&bv[0] = *(float4*)&Bs[kk][tx * 8];
            *(float4*)&bv[4] = *(float4*)&Bs[kk][tx * 8 + 4];
            #pragma unroll
            for (int i = 0; i < 8; i++)
                #pragma unroll
                for (int j = 0; j < 8; j++)
                    acc[i][j] += av[i] * bv[j];
        }
    }

    #pragma unroll
    for (int i = 0; i < 8; i++) {
        int m = bm + ty * 8 + i;
        #pragma unroll
        for (int j = 0; j < 8; j++) {
            int n = bn + tx * 8 + j;
            float v = acc[i][j] + bias[n];
            if (MODE == 0) {
                // n indexes (h, 3*hd): h = n/192, r = n%192
                int b = m >> 11;            // m = b*2048 + s
                int s = m & (SS - 1);
                int h = n / 192;
                int r = n - h * 192;
                int off = ((b * HH + h) * SS + s) * HDD;
                if (r < 64)       g_q[off + r]       = v;
                else if (r < 128) g_k[off + r - 64]  = v;
                else              g_v[off + r - 128] = v;
            } else {
                Cout[m * N + n] = v;
            }
        }
    }
}

// ---------------------------------------------------------------------------
// Flash-style causal attention, fp32.
// Grid: (S/64 q-tiles, B*H).  One CTA = 64 q-rows of one (b,h).
// 256 threads as 16x16; each thread owns a 4x4 patch of S/P and of O.
// Shared: Qs[d][i], KPs = K tile [d][j] overlaid with P tile [i][k], Vs[k][d].
// Exactly 48KB static shared.
// ---------------------------------------------------------------------------
__global__ __launch_bounds__(256)
void flash_attn()
{
    __shared__ float Qs [64 * 64];
    __shared__ float KPs[64 * 64];
    __shared__ float Vs [64 * 64];

    const int bh  = blockIdx.y;
    const int qt  = (int)gridDim.x - 1 - (int)blockIdx.x;  // big tiles first
    const int qs  = qt * 64;
    const int tid = threadIdx.x;
    const int tx  = tid & 15;
    const int ty  = tid >> 4;

    const float* qb = g_q + bh * SS * HDD;
    const float* kb = g_k + bh * SS * HDD;
    const float* vb = g_v + bh * SS * HDD;

    // Load Q tile transposed: Qs[d][i]
    #pragma unroll
    for (int r = 0; r < 4; r++) {
        int f  = tid + r * 256;
        int i  = f >> 4;
        int dq = (f & 15) << 2;
        float4 v4 = *(const float4*)(qb + (qs + i) * 64 + dq);
        Qs[(dq + 0) * 64 + i] = v4.x;
        Qs[(dq + 1) * 64 + i] = v4.y;
        Qs[(dq + 2) * 64 + i] = v4.z;
        Qs[(dq + 3) * 64 + i] = v4.w;
    }

    float o[4][4];
    float mrow[4], lrow[4];
    #pragma unroll
    for (int i = 0; i < 4; i++) {
        mrow[i] = -1e30f; lrow[i] = 0.f;
        #pragma unroll
        for (int j = 0; j < 4; j++) o[i][j] = 0.f;
    }

    for (int jt = 0; jt <= qt; jt++) {
        const int ks = jt * 64;
        __syncthreads();   // protect KPs/Vs reuse from previous iteration
        // Load K tile transposed KPs[d][j]; V tile natural Vs[k][d]
        #pragma unroll
        for (int r = 0; r < 4; r++) {
            int f  = tid + r * 256;
            int i  = f >> 4;
            int dq = (f & 15) << 2;
            float4 kv = *(const float4*)(kb + (ks + i) * 64 + dq);
            KPs[(dq + 0) * 64 + i] = kv.x;
            KPs[(dq + 1) * 64 + i] = kv.y;
            KPs[(dq + 2) * 64 + i] = kv.z;
            KPs[(dq + 3) * 64 + i] = kv.w;
            *(float4*)&Vs[i * 64 + dq] = *(const float4*)(vb + (ks + i) * 64 + dq);
        }
        __syncthreads();

        // S = Q K^T  (64x64, each thread 4x4)
        float sa[4][4];
        #pragma unroll
        for (int i = 0; i < 4; i++)
            #pragma unroll
            for (int j = 0; j < 4; j++) sa[i][j] = 0.f;

        #pragma unroll 16
        for (int kk = 0; kk < 64; kk++) {
            float4 qa = *(float4*)&Qs [kk * 64 + ty * 4];
            float4 ka = *(float4*)&KPs[kk * 64 + tx * 4];
            float qv[4] = {qa.x, qa.y, qa.z, qa.w};
            float kvv[4] = {ka.x, ka.y, ka.z, ka.w};
            #pragma unroll
            for (int i = 0; i < 4; i++)
                #pragma unroll
                for (int j = 0; j < 4; j++)
                    sa[i][j] += qv[i] * kvv[j];
        }

        // scale + causal mask (only diagonal tile can mask)
        const float scale = 0.125f;  // 1/sqrt(64)
        #pragma unroll
        for (int i = 0; i < 4; i++)
            #pragma unroll
            for (int j = 0; j < 4; j++) {
                sa[i][j] *= scale;
                if (jt == qt && (tx * 4 + j) > (ty * 4 + i)) sa[i][j] = -1e30f;
            }

        // online softmax update
        float p[4][4];
        #pragma unroll
        for (int i = 0; i < 4; i++) {
            float rm = fmaxf(fmaxf(sa[i][0], sa[i][1]), fmaxf(sa[i][2], sa[i][3]));
            rm = fmaxf(rm, __shfl_xor_sync(0xffffffffu, rm, 1));
            rm = fmaxf(rm, __shfl_xor_sync(0xffffffffu, rm, 2));
            rm = fmaxf(rm, __shfl_xor_sync(0xffffffffu, rm, 4));
            rm = fmaxf(rm, __shfl_xor_sync(0xffffffffu, rm, 8));
            float mnew  = fmaxf(mrow[i], rm);
            float alpha = __expf(mrow[i] - mnew);
            mrow[i] = mnew;
            float rs = 0.f;
            #pragma unroll
            for (int j = 0; j < 4; j++) {
                p[i][j] = __expf(sa[i][j] - mnew);
                rs += p[i][j];
            }
            rs += __shfl_xor_sync(0xffffffffu, rs, 1);
            rs += __shfl_xor_sync(0xffffffffu, rs, 2);
            rs += __shfl_xor_sync(0xffffffffu, rs, 4);
            rs += __shfl_xor_sync(0xffffffffu, rs, 8);
            lrow[i] = lrow[i] * alpha + rs;
            #pragma unroll
            for (int j = 0; j < 4; j++) o[i][j] *= alpha;
        }

        __syncthreads();   // all S-gemm reads of KPs done before P overwrites it
        // Store P into KPs as Ps[i][k]
        #pragma unroll
        for (int i = 0; i < 4; i++) {
            float4 pv = make_float4(p[i][0], p[i][1], p[i][2], p[i][3]);
            *(float4*)&KPs[(ty * 4 + i) * 64 + tx * 4] = pv;
        }
        __syncthreads();

        // O += P @ V
        #pragma unroll 16
        for (int kk = 0; kk < 64; kk++) {
            float a0 = KPs[(ty * 4 + 0) * 64 + kk];
            float a1 = KPs[(ty * 4 + 1) * 64 + kk];
            float a2 = KPs[(ty * 4 + 2) * 64 + kk];
            float a3 = KPs[(ty * 4 + 3) * 64 + kk];
            float4 vv = *(float4*)&Vs[kk * 64 + tx * 4];
            float vj[4] = {vv.x, vv.y, vv.z, vv.w};
            #pragma unroll
            for (int j = 0; j < 4; j++) {
                o[0][j] += a0 * vj[j];
                o[1][j] += a1 * vj[j];
                o[2][j] += a2 * vj[j];
                o[3][j] += a3 * vj[j];
            }
        }
    }

    // Epilogue: O /= l, write to g_ao[b][s][h*64+hd]
    const int b = bh >> 4;
    const int h = bh & 15;
    #pragma unroll
    for (int i = 0; i < 4; i++) {
        float inv = 1.0f / lrow[i];
        int srow = qs + ty * 4 + i;
        float4 ov = make_float4(o[i][0] * inv, o[i][1] * inv,
                                o[i][2] * inv, o[i][3] * inv);
        *(float4*)(g_ao + (b * SS + srow) * DD + h * 64 + tx * 4) = ov;
    }
}

// ---------------------------------------------------------------------------
// Launch: x, W_qkv, b_qkv, W_out, b_out  ->  out [B,S,D] fp32
// ---------------------------------------------------------------------------
extern "C" void kernel_launch(void* const* d_in, const int* in_sizes, int n_in,
                              void* d_out, int out_size)
{
    (void)in_sizes; (void)n_in; (void)out_size;
    const float* x    = (const float*)d_in[0];
    const float* Wqkv = (const float*)d_in[1];
    const float* bqkv = (const float*)d_in[2];
    const float* Wout = (const float*)d_in[3];
    const float* bout = (const float*)d_in[4];
    float* out = (float*)d_out;

    // 1) QKV projection: [4096,1024] @ [1024,3072] + bias -> scatter q/k/v
    sgemm128<0><<<dim3(3 * DD / 128, BB * SS / 128), 256>>>(
        x, Wqkv, bqkv, nullptr, BB * SS, 3 * DD, DD);

    // 2) Causal flash attention -> g_ao
    flash_attn<<<dim3(SS / 64, BHH), 256>>>();

    // 3) Output projection: [4096,1024] @ [1024,1024] + bias -> out
    sgemm128<1><<<dim3(DD / 128, BB * SS / 128), 256>>>(
        nullptr, Wout, bout, out, BB * SS, DD, DD);
}

// round 4
// speedup vs baseline: 2.8482x; 2.8482x over previous
#include <cuda_runtime.h>
#include <cuda_bf16.h>
#include <cstdint>

#define BB 2
#define SS 2048
#define DD 1024
#define HH 16
#define HDD 64
#define BHH 32
#define MTOT 4096
#define NQKV 3072

typedef __nv_bfloat16 bf16;
typedef __nv_bfloat162 bf162;

// split operands (__device__ globals: allocation-free rule), 16B aligned
__device__ __align__(16) bf16 g_xhi[MTOT*DD], g_xlo[MTOT*DD];
__device__ __align__(16) bf16 g_wqh[DD*NQKV], g_wql[DD*NQKV];   // W_qkv natural [k][n]
__device__ __align__(16) bf16 g_woh[DD*DD],   g_wol[DD*DD];     // W_out  natural [k][n]
__device__ __align__(16) bf16 g_qh[BHH*SS*HDD], g_ql[BHH*SS*HDD];  // [bh][s][hd]
__device__ __align__(16) bf16 g_kh[BHH*SS*HDD], g_kl[BHH*SS*HDD];
__device__ __align__(16) bf16 g_vh[BHH*SS*HDD], g_vl[BHH*SS*HDD];
__device__ __align__(16) bf16 g_aoh[MTOT*DD], g_aol[MTOT*DD];      // [b*s][d]

// ---------------- helpers ----------------
__device__ __forceinline__ uint32_t smem_u32(const void* p){
    uint32_t a;
    asm("{ .reg .u64 t; cvta.to.shared.u64 t, %1; cvt.u32.u64 %0, t; }":"=r"(a):"l"(p));
    return a;
}
__device__ __forceinline__ void cp16(uint32_t d, const void* s){
    asm volatile("cp.async.cg.shared.global [%0], [%1], 16;"::"r"(d),"l"(s));
}
__device__ __forceinline__ void cp_commit(){ asm volatile("cp.async.commit_group;":::"memory"); }
template<int N> __device__ __forceinline__ void cp_wait(){
    asm volatile("cp.async.wait_group %0;"::"n"(N):"memory");
}
__device__ __forceinline__ void ldsm4(uint32_t* r, uint32_t a){
    asm volatile("ldmatrix.sync.aligned.m8n8.x4.shared.b16 {%0,%1,%2,%3}, [%4];"
        :"=r"(r[0]),"=r"(r[1]),"=r"(r[2]),"=r"(r[3]):"r"(a));
}
__device__ __forceinline__ void ldsm4t(uint32_t* r, uint32_t a){
    asm volatile("ldmatrix.sync.aligned.m8n8.x4.trans.shared.b16 {%0,%1,%2,%3}, [%4];"
        :"=r"(r[0]),"=r"(r[1]),"=r"(r[2]),"=r"(r[3]):"r"(a));
}
__device__ __forceinline__ void mma_bf(float* c, const uint32_t* a, uint32_t b0, uint32_t b1){
    asm volatile("mma.sync.aligned.m16n8k16.row.col.f32.bf16.bf16.f32 "
        "{%0,%1,%2,%3}, {%4,%5,%6,%7}, {%8,%9}, {%0,%1,%2,%3};"
        :"+f"(c[0]),"+f"(c[1]),"+f"(c[2]),"+f"(c[3])
        :"r"(a[0]),"r"(a[1]),"r"(a[2]),"r"(a[3]),"r"(b0),"r"(b1));
}
__device__ __forceinline__ uint32_t packbf(float x, float y){
    bf162 t = __floats2bfloat162_rn(x, y);
    return *reinterpret_cast<uint32_t*>(&t);
}
__device__ __forceinline__ float bfhi(float v){
    return __bfloat162float(__float2bfloat16(v));
}

// ---------------- prep: fp32 -> (hi,lo) bf16 ----------------
template<int SEL>
__global__ __launch_bounds__(256)
void split_k(const float* __restrict__ src, int n4){
    bf16* hi = (SEL==0)? g_xhi : (SEL==1)? g_wqh : g_woh;
    bf16* lo = (SEL==0)? g_xlo : (SEL==1)? g_wql : g_wol;
    int i = blockIdx.x*256 + threadIdx.x;
    if (i < n4){
        float4 v = reinterpret_cast<const float4*>(src)[i];
        float hx=bfhi(v.x), hy=bfhi(v.y), hz=bfhi(v.z), hw=bfhi(v.w);
        reinterpret_cast<uint32_t*>(hi)[i*2+0] = packbf(hx,hy);
        reinterpret_cast<uint32_t*>(hi)[i*2+1] = packbf(hz,hw);
        reinterpret_cast<uint32_t*>(lo)[i*2+0] = packbf(v.x-hx, v.y-hy);
        reinterpret_cast<uint32_t*>(lo)[i*2+1] = packbf(v.z-hz, v.w-hw);
    }
}

// ---------------- split-bf16 GEMM: 128x128 tile, 8 warps ----------------
// A tile: 128 rows x (32hi|32lo|pad) bf16, row = 144B (9x16B)  -> 18432 B
// B tile:  32 k    x (128hi|128lo|pad) bf16, row = 528B (33x16B) -> 16896 B
#define GSTAGE 35328
#define GSMEM  (2*GSTAGE)

template<int MODE>
__global__ __launch_bounds__(256)
void gemm_mma(const float* __restrict__ bias, float* __restrict__ Cout){
    extern __shared__ char smem[];
    const bf16* Ahi = (MODE==0)? g_xhi : g_aoh;
    const bf16* Alo = (MODE==0)? g_xlo : g_aol;
    const bf16* Bhi = (MODE==0)? g_wqh : g_woh;
    const bf16* Blo = (MODE==0)? g_wql : g_wol;
    const int N = (MODE==0)? NQKV : DD;

    const int bm = blockIdx.y*128, bn = blockIdx.x*128;
    const int tid = threadIdx.x, lane = tid&31, wid = tid>>5;
    const int wm = wid>>2, wn = wid&3;   // warp tile 64(M) x 32(N)
    uint32_t sb = smem_u32(smem);

    float acc[4][4][4];
    #pragma unroll
    for (int a=0;a<4;a++)
        #pragma unroll
        for (int b=0;b<4;b++)
            #pragma unroll
            for (int c=0;c<4;c++) acc[a][b][c]=0.f;

    // stage loader
    auto load_stage = [&](int t, int s){
        uint32_t as  = sb + s*GSTAGE;
        uint32_t bs2 = as + 18432;
        int k0 = t*32;
        #pragma unroll
        for (int i=0;i<4;i++){
            int id = i*256 + tid;
            int row = id>>3, seg = id&7;
            const bf16* src = (seg<4)? (Ahi + (size_t)(bm+row)*DD + k0 + seg*8)
                                     : (Alo + (size_t)(bm+row)*DD + k0 + (seg-4)*8);
            cp16(as + row*144 + seg*16, src);
        }
        #pragma unroll
        for (int i=0;i<4;i++){
            int id = i*256 + tid;
            int row = id>>5, seg = id&31;
            const bf16* src = (seg<16)? (Bhi + (size_t)(k0+row)*N + bn + seg*8)
                                      : (Blo + (size_t)(k0+row)*N + bn + (seg-16)*8);
            cp16(bs2 + row*528 + seg*16, src);
        }
        cp_commit();
    };

    load_stage(0,0);
    for (int t=0; t<32; t++){
        if (t<31){ load_stage(t+1,(t+1)&1); cp_wait<1>(); }
        else     { cp_wait<0>(); }
        __syncthreads();
        uint32_t as  = sb + (t&1)*GSTAGE;
        uint32_t bs2 = as + 18432;
        #pragma unroll
        for (int k16=0;k16<2;k16++){
            uint32_t ah[4][4], al[4][4];
            #pragma unroll
            for (int mf=0;mf<4;mf++){
                uint32_t ad = as + (uint32_t)(wm*64+mf*16+(lane&15))*144
                            + k16*32 + ((lane>>4)<<4);
                ldsm4(ah[mf], ad);
                ldsm4(al[mf], ad+64);
            }
            uint32_t bhf[4][2], blf[4][2];
            #pragma unroll
            for (int np=0;np<2;np++){
                uint32_t kk = (uint32_t)(k16*16 + (lane&15));
                uint32_t bd = bs2 + kk*528
                            + ((uint32_t)(wn*32 + np*16 + ((lane>>4)<<3))<<1);
                uint32_t t4[4];
                ldsm4t(t4, bd);
                bhf[np*2][0]=t4[0]; bhf[np*2][1]=t4[1];
                bhf[np*2+1][0]=t4[2]; bhf[np*2+1][1]=t4[3];
                ldsm4t(t4, bd+256);
                blf[np*2][0]=t4[0]; blf[np*2][1]=t4[1];
                blf[np*2+1][0]=t4[2]; blf[np*2+1][1]=t4[3];
            }
            #pragma unroll
            for (int mf=0;mf<4;mf++)
                #pragma unroll
                for (int nf=0;nf<4;nf++){
                    mma_bf(acc[mf][nf], ah[mf], bhf[nf][0], bhf[nf][1]);
                    mma_bf(acc[mf][nf], ah[mf], blf[nf][0], blf[nf][1]);
                    mma_bf(acc[mf][nf], al[mf], bhf[nf][0], bhf[nf][1]);
                }
        }
        __syncthreads();
    }

    // epilogue: c0,c1=(row, col,col+1), c2,c3=(row+8, ...)
    #pragma unroll
    for (int mf=0;mf<4;mf++){
        #pragma unroll
        for (int nf=0;nf<4;nf++){
            int n0 = bn + wn*32 + nf*8 + ((lane&3)<<1);
            float b0v = bias[n0], b1v = bias[n0+1];
            #pragma unroll
            for (int hf=0; hf<2; hf++){
                int m = bm + wm*64 + mf*16 + (lane>>2) + hf*8;
                float v0 = acc[mf][nf][hf*2+0] + b0v;
                float v1 = acc[mf][nf][hf*2+1] + b1v;
                if (MODE==0){
                    int b = m>>11, s = m&(SS-1);
                    int h = n0/192, r = n0 - h*192;
                    float h0 = bfhi(v0), h1 = bfhi(v1);
                    uint32_t ph = packbf(h0,h1), pl = packbf(v0-h0, v1-h1);
                    size_t base = ((size_t)(b*HH+h)*SS + s)*HDD;
                    if (r < 64){
                        *(uint32_t*)(g_qh+base+r) = ph;
                        *(uint32_t*)(g_ql+base+r) = pl;
                    } else if (r < 128){
                        *(uint32_t*)(g_kh+base+r-64) = ph;
                        *(uint32_t*)(g_kl+base+r-64) = pl;
                    } else {
                        *(uint32_t*)(g_vh+base+r-128) = ph;
                        *(uint32_t*)(g_vl+base+r-128) = pl;
                    }
                } else {
                    float2 ov; ov.x = v0; ov.y = v1;
                    *(float2*)(Cout + (size_t)m*DD + n0) = ov;
                }
            }
        }
    }
}

// ---------------- flash attention on mma.sync ----------------
// CTA: 64 q-rows of one (b,h). 4 warps; warp = 16 q-rows x full 64 cols.
// Tiles Q/K/V: 64 rows x (64hi|64lo|pad) bf16, row = 272B (17x16B) -> 17408 B each.
#define ATILE 17408
#define ASMEM (3*ATILE)

__global__ __launch_bounds__(128)
void attn_mma(){
    extern __shared__ char smem[];
    const int bh = blockIdx.y;
    const int qt = (int)gridDim.x - 1 - (int)blockIdx.x;   // big tiles first
    const int qs = qt*64;
    const int tid = threadIdx.x, lane = tid&31, wid = tid>>5;
    uint32_t sb = smem_u32(smem);
    uint32_t Qs = sb, Ks = sb + ATILE, Vs = sb + 2*ATILE;
    const size_t hb = (size_t)bh*SS*HDD;
    const bf16 *qh = g_qh+hb, *ql = g_ql+hb, *kh = g_kh+hb, *kl = g_kl+hb,
               *vh = g_vh+hb, *vl = g_vl+hb;

    #pragma unroll
    for (int i=0;i<8;i++){
        int id = i*128+tid, row = id>>4, seg = id&15;
        const bf16* src = (seg<8)? qh + (size_t)(qs+row)*HDD + seg*8
                                 : ql + (size_t)(qs+row)*HDD + (seg-8)*8;
        cp16(Qs + row*272 + seg*16, src);
    }
    cp_commit();

    float o[8][4];
    #pragma unroll
    for (int a=0;a<8;a++)
        #pragma unroll
        for (int b=0;b<4;b++) o[a][b]=0.f;
    float m0 = -1e30f, m1 = -1e30f, l0 = 0.f, l1 = 0.f;
    const int rg0 = qs + wid*16 + (lane>>2);
    const int rg1 = rg0 + 8;

    for (int jt=0; jt<=qt; jt++){
        int ks = jt*64;
        #pragma unroll
        for (int i=0;i<8;i++){
            int id = i*128+tid, row = id>>4, seg = id&15;
            const bf16* src = (seg<8)? kh + (size_t)(ks+row)*HDD + seg*8
                                     : kl + (size_t)(ks+row)*HDD + (seg-8)*8;
            cp16(Ks + row*272 + seg*16, src);
        }
        #pragma unroll
        for (int i=0;i<8;i++){
            int id = i*128+tid, row = id>>4, seg = id&15;
            const bf16* src = (seg<8)? vh + (size_t)(ks+row)*HDD + seg*8
                                     : vl + (size_t)(ks+row)*HDD + (seg-8)*8;
            cp16(Vs + row*272 + seg*16, src);
        }
        cp_commit();
        cp_wait<0>();
        __syncthreads();

        // S = Q K^T (warp: 16 rows x 64 cols, K-dim 64)
        float s[8][4];
        #pragma unroll
        for (int a=0;a<8;a++)
            #pragma unroll
            for (int b=0;b<4;b++) s[a][b]=0.f;
        #pragma unroll
        for (int kc=0; kc<4; kc++){
            uint32_t qhf[4], qlf[4];
            uint32_t qa = Qs + (uint32_t)(wid*16 + (lane&15))*272
                        + kc*32 + ((lane>>4)<<4);
            ldsm4(qhf, qa); ldsm4(qlf, qa+128);
            #pragma unroll
            for (int np=0; np<4; np++){
                uint32_t row = (uint32_t)(np*16 + ((lane>>4)<<3) + (lane&7));
                uint32_t ka = Ks + row*272 + kc*32 + (((lane>>3)&1)<<4);
                uint32_t t4[4], u4[4];
                ldsm4(t4, ka); ldsm4(u4, ka+128);
                mma_bf(s[np*2],   qhf, t4[0], t4[1]);
                mma_bf(s[np*2+1], qhf, t4[2], t4[3]);
                mma_bf(s[np*2],   qhf, u4[0], u4[1]);
                mma_bf(s[np*2+1], qhf, u4[2], u4[3]);
                mma_bf(s[np*2],   qlf, t4[0], t4[1]);
                mma_bf(s[np*2+1], qlf, t4[2], t4[3]);
            }
        }
        // scale + causal mask (diagonal tile only)
        const bool dia = (jt==qt);
        #pragma unroll
        for (int nf=0; nf<8; nf++){
            int c = ks + nf*8 + ((lane&3)<<1);
            #pragma unroll
            for (int r=0;r<4;r++) s[nf][r] *= 0.125f;
            if (dia){
                if (c   > rg0) s[nf][0] = -1e30f;
                if (c+1 > rg0) s[nf][1] = -1e30f;
                if (c   > rg1) s[nf][2] = -1e30f;
                if (c+1 > rg1) s[nf][3] = -1e30f;
            }
        }
        // row maxima (2 rows/thread, reduce across quad)
        float mx0 = -1e30f, mx1 = -1e30f;
        #pragma unroll
        for (int nf=0;nf<8;nf++){
            mx0 = fmaxf(mx0, fmaxf(s[nf][0], s[nf][1]));
            mx1 = fmaxf(mx1, fmaxf(s[nf][2], s[nf][3]));
        }
        mx0 = fmaxf(mx0, __shfl_xor_sync(0xffffffffu, mx0, 1));
        mx0 = fmaxf(mx0, __shfl_xor_sync(0xffffffffu, mx0, 2));
        mx1 = fmaxf(mx1, __shfl_xor_sync(0xffffffffu, mx1, 1));
        mx1 = fmaxf(mx1, __shfl_xor_sync(0xffffffffu, mx1, 2));
        float m0n = fmaxf(m0, mx0), m1n = fmaxf(m1, mx1);
        float a0 = __expf(m0 - m0n), a1 = __expf(m1 - m1n);
        m0 = m0n; m1 = m1n;

        // P = exp(S - m): split hi/lo, pack A-frags in registers
        float sum0 = 0.f, sum1 = 0.f;
        uint32_t ph[4][4], pl[4][4];
        #pragma unroll
        for (int kc=0; kc<4; kc++){
            #pragma unroll
            for (int half=0; half<2; half++){
                int nf = kc*2 + half;
                float p0 = __expf(s[nf][0]-m0n), p1 = __expf(s[nf][1]-m0n);
                float p2 = __expf(s[nf][2]-m1n), p3 = __expf(s[nf][3]-m1n);
                sum0 += p0+p1; sum1 += p2+p3;
                float h0=bfhi(p0), h1=bfhi(p1), h2=bfhi(p2), h3=bfhi(p3);
                ph[kc][half*2+0] = packbf(h0,h1);
                ph[kc][half*2+1] = packbf(h2,h3);
                pl[kc][half*2+0] = packbf(p0-h0, p1-h1);
                pl[kc][half*2+1] = packbf(p2-h2, p3-h3);
            }
        }
        sum0 += __shfl_xor_sync(0xffffffffu, sum0, 1);
        sum0 += __shfl_xor_sync(0xffffffffu, sum0, 2);
        sum1 += __shfl_xor_sync(0xffffffffu, sum1, 1);
        sum1 += __shfl_xor_sync(0xffffffffu, sum1, 2);
        l0 = l0*a0 + sum0; l1 = l1*a1 + sum1;
        #pragma unroll
        for (int nf=0;nf<8;nf++){
            o[nf][0]*=a0; o[nf][1]*=a0; o[nf][2]*=a1; o[nf][3]*=a1;
        }

        // O += P @ V
        #pragma unroll
        for (int kc=0; kc<4; kc++){
            #pragma unroll
            for (int g=0; g<4; g++){
                uint32_t va = Vs + (uint32_t)(kc*16 + (lane&15))*272
                            + ((uint32_t)(g*16 + ((lane>>4)<<3))<<1);
                uint32_t vh4[4], vl4[4];
                ldsm4t(vh4, va); ldsm4t(vl4, va+128);
                mma_bf(o[g*2],   ph[kc], vh4[0], vh4[1]);
                mma_bf(o[g*2],   ph[kc], vl4[0], vl4[1]);
                mma_bf(o[g*2],   pl[kc], vh4[0], vh4[1]);
                mma_bf(o[g*2+1], ph[kc], vh4[2], vh4[3]);
                mma_bf(o[g*2+1], ph[kc], vl4[2], vl4[3]);
                mma_bf(o[g*2+1], pl[kc], vh4[2], vh4[3]);
            }
        }
        __syncthreads();   // done reading K/V before next tile overwrites
    }

    // epilogue: o/l -> split bf16 -> g_aoh/g_aol[b*s][h*64+d]
    const int b = bh >> 4, h = bh & 15;
    float inv0 = 1.0f/l0, inv1 = 1.0f/l1;
    int r0 = qs + wid*16 + (lane>>2);
    #pragma unroll
    for (int nf=0; nf<8; nf++){
        int n0 = nf*8 + ((lane&3)<<1);
        float v0 = o[nf][0]*inv0, v1 = o[nf][1]*inv0;
        float h0 = bfhi(v0), h1 = bfhi(v1);
        size_t idx0 = ((size_t)(b*SS + r0))*DD + h*64 + n0;
        *(uint32_t*)(g_aoh + idx0) = packbf(h0,h1);
        *(uint32_t*)(g_aol + idx0) = packbf(v0-h0, v1-h1);
        float v2 = o[nf][2]*inv1, v3 = o[nf][3]*inv1;
        float h2 = bfhi(v2), h3 = bfhi(v3);
        size_t idx1 = ((size_t)(b*SS + r0 + 8))*DD + h*64 + n0;
        *(uint32_t*)(g_aoh + idx1) = packbf(h2,h3);
        *(uint32_t*)(g_aol + idx1) = packbf(v2-h2, v3-h3);
    }
}

// ---------------------------------------------------------------------------
extern "C" void kernel_launch(void* const* d_in, const int* in_sizes, int n_in,
                              void* d_out, int out_size) {
    (void)in_sizes; (void)n_in; (void)out_size;
    const float* x    = (const float*)d_in[0];
    const float* Wqkv = (const float*)d_in[1];
    const float* bqkv = (const float*)d_in[2];
    const float* Wout = (const float*)d_in[3];
    const float* bout = (const float*)d_in[4];
    float* out = (float*)d_out;

    cudaFuncSetAttribute(gemm_mma<0>, cudaFuncAttributeMaxDynamicSharedMemorySize, GSMEM);
    cudaFuncSetAttribute(gemm_mma<1>, cudaFuncAttributeMaxDynamicSharedMemorySize, GSMEM);
    cudaFuncSetAttribute(attn_mma,    cudaFuncAttributeMaxDynamicSharedMemorySize, ASMEM);

    // 0) split fp32 operands into (hi,lo) bf16
    split_k<0><<<(MTOT*DD/4 + 255)/256, 256>>>(x,    MTOT*DD/4);
    split_k<1><<<(DD*NQKV/4 + 255)/256, 256>>>(Wqkv, DD*NQKV/4);
    split_k<2><<<(DD*DD/4  + 255)/256, 256>>>(Wout,  DD*DD/4);

    // 1) QKV projection -> split q/k/v
    gemm_mma<0><<<dim3(NQKV/128, MTOT/128), 256, GSMEM>>>(bqkv, nullptr);

    // 2) causal attention -> g_aoh/g_aol
    attn_mma<<<dim3(SS/64, BHH), 128, ASMEM>>>();

    // 3) output projection -> out
    gemm_mma<1><<<dim3(DD/128, MTOT/128), 256, GSMEM>>>(bout, out);
}